// round 1
// baseline (speedup 1.0000x reference)
#include <cuda_runtime.h>
#include <cuda_bf16.h>

// Problem dims (fixed by the dataset)
#define K_DIM   512
#define N_TOK   16384
#define M_CODES 2048

// Scratch (no cudaMalloc allowed)
__device__ float g_esq[N_TOK];
__device__ float g_tsq[M_CODES];
__device__ int   g_zidx[N_TOK];

// ---------------------------------------------------------------------------
// Squared-norm kernel: one warp per row, which==0 -> g_esq, which==1 -> g_tsq
// ---------------------------------------------------------------------------
__global__ void sqnorm_kernel(const float* __restrict__ x, int rows, int which) {
    int warp = (blockIdx.x * blockDim.x + threadIdx.x) >> 5;
    int lane = threadIdx.x & 31;
    if (warp >= rows) return;
    const float* p = x + (size_t)warp * K_DIM;
    float s = 0.f;
#pragma unroll
    for (int i = 0; i < K_DIM / 32; i++) {
        float v = p[lane + i * 32];
        s = fmaf(v, v, s);
    }
#pragma unroll
    for (int o = 16; o > 0; o >>= 1) s += __shfl_xor_sync(0xffffffffu, s, o);
    if (lane == 0) {
        if (which == 0) g_esq[warp] = s;
        else            g_tsq[warp] = s;
    }
}

// ---------------------------------------------------------------------------
// Fused SGEMM + argmin.
// Block: 256 threads (16x16). Tile: BM=64 rows x BN=128 codes, BK=32.
// Each thread: TM=4 rows x TN=8 cols register block.
// dist = (e_sq - 2*dot) + t_sq  (reference expression order, fp32 throughout)
// argmin with first-index tie-break (strict <, ascending m; cross-thread
// reduction breaks ties toward smaller index).
// ---------------------------------------------------------------------------
#define BM 64
#define BN 128
#define BK 32
#define TM 4
#define TN 8
#define APAD 4
#define BPAD 4

__global__ __launch_bounds__(256) void argmin_gemm_kernel(
    const float* __restrict__ E, const float* __restrict__ T)
{
    __shared__ __align__(16) float As[BK][BM + APAD];  // k-major
    __shared__ __align__(16) float Bs[BK][BN + BPAD];  // k-major
    __shared__ float rbest[BM][16];
    __shared__ int   ridx [BM][16];

    const int tid = threadIdx.x;
    const int tx  = tid & 15;   // column group
    const int ty  = tid >> 4;   // row group
    const int row0 = blockIdx.x * BM;

    float best[TM];
    int   bidx[TM];
#pragma unroll
    for (int i = 0; i < TM; i++) { best[i] = 3.4e38f; bidx[i] = 0; }

    float esq[TM];
#pragma unroll
    for (int i = 0; i < TM; i++) esq[i] = g_esq[row0 + ty * TM + i];

    for (int m0 = 0; m0 < M_CODES; m0 += BN) {
        float acc[TM][TN];
#pragma unroll
        for (int i = 0; i < TM; i++)
#pragma unroll
            for (int j = 0; j < TN; j++) acc[i][j] = 0.f;

        for (int k0 = 0; k0 < K_DIM; k0 += BK) {
            // Load A tile (BM x BK = 2048 floats): 2 float4 per thread,
            // transposed store into k-major As.
#pragma unroll
            for (int l = 0; l < 2; l++) {
                int id = tid + l * 256;          // 0..511
                int r  = id >> 3;                // row in tile (0..63)
                int q  = id & 7;                 // float4 index along k
                float4 v = *reinterpret_cast<const float4*>(
                    &E[(size_t)(row0 + r) * K_DIM + k0 + q * 4]);
                As[q * 4 + 0][r] = v.x;
                As[q * 4 + 1][r] = v.y;
                As[q * 4 + 2][r] = v.z;
                As[q * 4 + 3][r] = v.w;
            }
            // Load B tile (BN x BK = 4096 floats): 4 float4 per thread.
#pragma unroll
            for (int l = 0; l < 4; l++) {
                int id = tid + l * 256;          // 0..1023
                int r  = id >> 3;                // code row in tile (0..127)
                int q  = id & 7;
                float4 v = *reinterpret_cast<const float4*>(
                    &T[(size_t)(m0 + r) * K_DIM + k0 + q * 4]);
                Bs[q * 4 + 0][r] = v.x;
                Bs[q * 4 + 1][r] = v.y;
                Bs[q * 4 + 2][r] = v.z;
                Bs[q * 4 + 3][r] = v.w;
            }
            __syncthreads();

#pragma unroll
            for (int kk = 0; kk < BK; kk++) {
                float4 av = *reinterpret_cast<const float4*>(&As[kk][ty * TM]);
                float4 b0 = *reinterpret_cast<const float4*>(&Bs[kk][tx * TN]);
                float4 b1 = *reinterpret_cast<const float4*>(&Bs[kk][tx * TN + 4]);
                float a[TM] = {av.x, av.y, av.z, av.w};
                float b[TN] = {b0.x, b0.y, b0.z, b0.w, b1.x, b1.y, b1.z, b1.w};
#pragma unroll
                for (int i = 0; i < TM; i++)
#pragma unroll
                    for (int j = 0; j < TN; j++)
                        acc[i][j] = fmaf(a[i], b[j], acc[i][j]);
            }
            __syncthreads();
        }

        // dist + per-thread argmin update (m ascending; strict < keeps first)
#pragma unroll
        for (int j = 0; j < TN; j++) {
            int m = m0 + tx * TN + j;
            float tsq = g_tsq[m];
#pragma unroll
            for (int i = 0; i < TM; i++) {
                float d = (esq[i] - 2.0f * acc[i][j]) + tsq;
                if (d < best[i]) { best[i] = d; bidx[i] = m; }
            }
        }
    }

    // Cross-thread reduction over tx (tie -> smaller index)
#pragma unroll
    for (int i = 0; i < TM; i++) {
        rbest[ty * TM + i][tx] = best[i];
        ridx [ty * TM + i][tx] = bidx[i];
    }
    __syncthreads();
    if (tid < BM) {
        float b = rbest[tid][0];
        int  bi = ridx [tid][0];
#pragma unroll
        for (int t = 1; t < 16; t++) {
            float v = rbest[tid][t];
            int  vi = ridx [tid][t];
            if (v < b || (v == b && vi < bi)) { b = v; bi = vi; }
        }
        g_zidx[row0 + tid] = bi;
    }
}

// ---------------------------------------------------------------------------
// Gather: quant[n] = templat[zidx[n]]; optionally write zidx tail as float.
// One block per row, 128 threads x float4 = 512 floats.
// ---------------------------------------------------------------------------
__global__ void gather_kernel(const float* __restrict__ T,
                              float* __restrict__ outq,
                              float* __restrict__ outi,
                              int write_idx)
{
    int n = blockIdx.x;
    int zi = g_zidx[n];
    const float4* src = reinterpret_cast<const float4*>(T + (size_t)zi * K_DIM);
    float4* dst = reinterpret_cast<float4*>(outq + (size_t)n * K_DIM);
    dst[threadIdx.x] = src[threadIdx.x];
    if (write_idx && threadIdx.x == 0) outi[n] = (float)zi;
}

// ---------------------------------------------------------------------------
extern "C" void kernel_launch(void* const* d_in, const int* in_sizes, int n_in,
                              void* d_out, int out_size)
{
    const float* E = (const float*)d_in[0];  // (16384, 512)
    const float* T = (const float*)d_in[1];  // (2048, 512)
    float* out = (float*)d_out;

    // Row squared norms
    sqnorm_kernel<<<N_TOK / 8, 256>>>(E, N_TOK, 0);
    sqnorm_kernel<<<M_CODES / 8, 256>>>(T, M_CODES, 1);

    // Fused distance GEMM + argmin
    argmin_gemm_kernel<<<N_TOK / BM, 256>>>(E, T);

    // Gather + optional index tail
    int write_idx = (out_size >= N_TOK * K_DIM + N_TOK) ? 1 : 0;
    float* outi = out + (size_t)N_TOK * K_DIM;
    gather_kernel<<<N_TOK, 128>>>(T, out, outi, write_idx);
}

// round 2
// speedup vs baseline: 1.5729x; 1.5729x over previous
#include <cuda_runtime.h>
#include <cuda_bf16.h>

#define K_DIM   512
#define N_TOK   16384
#define M_CODES 2048

// Scratch (no cudaMalloc allowed)
__device__ float g_esq[N_TOK];
__device__ float g_tsq[M_CODES];
__device__ unsigned long long g_best[N_TOK];

// ---------------------------------------------------------------------------
// Init: g_best = +inf packed
// ---------------------------------------------------------------------------
__global__ void init_best_kernel() {
    int i = blockIdx.x * blockDim.x + threadIdx.x;
    if (i < N_TOK) g_best[i] = 0xFFFFFFFFFFFFFFFFull;
}

// ---------------------------------------------------------------------------
// Squared-norm kernel: one warp per row
// ---------------------------------------------------------------------------
__global__ void sqnorm_kernel(const float* __restrict__ x, int rows, int which) {
    int warp = (blockIdx.x * blockDim.x + threadIdx.x) >> 5;
    int lane = threadIdx.x & 31;
    if (warp >= rows) return;
    const float* p = x + (size_t)warp * K_DIM;
    float s = 0.f;
#pragma unroll
    for (int i = 0; i < K_DIM / 32; i++) {
        float v = p[lane + i * 32];
        s = fmaf(v, v, s);
    }
#pragma unroll
    for (int o = 16; o > 0; o >>= 1) s += __shfl_xor_sync(0xffffffffu, s, o);
    if (lane == 0) {
        if (which == 0) g_esq[warp] = s;
        else            g_tsq[warp] = s;
    }
}

// ---------------------------------------------------------------------------
// Fused SGEMM + argmin, M-split across grid.y, merged via packed atomicMin.
// Block: 128 threads (16x8). Tile: BM=64 x BN=128, BK=16 double-buffered.
// Micro-tile 8x8 per thread: 64 FFMA per 4 LDS.128.
// dist = (esq - 2*acc) + tsq, fp32, k ascending -> identical values to the
// verified round-1 kernel.
// ---------------------------------------------------------------------------
#define BM 64
#define BN 128
#define BK 16
#define AST (BM + 4)   // 68: k-stride for As (conflict-free pattern)
#define BST (BN + 4)   // 132

__global__ __launch_bounds__(128, 3) void argmin_gemm_kernel(
    const float* __restrict__ E, const float* __restrict__ T)
{
    __shared__ __align__(16) float As[2][BK][AST];
    __shared__ __align__(16) float Bs[2][BK][BST];

    const int tid = threadIdx.x;
    const int tx  = tid & 15;    // 0..15 : column group (8 cols each)
    const int ty  = tid >> 4;    // 0..7  : row group (8 rows each)
    const int row0 = blockIdx.x * BM;
    const int col0 = blockIdx.y * BN;

    // A tile: 64 rows x 16 k. 2 threads per row, 2 float4 each.
    const int ar = tid >> 1;            // row 0..63
    const int aq = (tid & 1) * 2;       // float4 index base (0 or 2)
    // B tile: 128 rows x 16 k. 1 thread per row, 4 float4.
    const int br = tid;

    const float* Aptr = E + (size_t)(row0 + ar) * K_DIM + aq * 4;
    const float* Bptr = T + (size_t)(col0 + br) * K_DIM;

    float acc[8][8];
#pragma unroll
    for (int i = 0; i < 8; i++)
#pragma unroll
        for (int j = 0; j < 8; j++) acc[i][j] = 0.f;

    // ---- prologue: stage 0 into buffer 0 ----
    {
        float4 pa0 = *reinterpret_cast<const float4*>(Aptr);
        float4 pa1 = *reinterpret_cast<const float4*>(Aptr + 4);
        float4 pb[4];
#pragma unroll
        for (int u = 0; u < 4; u++)
            pb[u] = *reinterpret_cast<const float4*>(Bptr + u * 4);

        As[0][aq * 4 + 0][ar] = pa0.x;
        As[0][aq * 4 + 1][ar] = pa0.y;
        As[0][aq * 4 + 2][ar] = pa0.z;
        As[0][aq * 4 + 3][ar] = pa0.w;
        As[0][aq * 4 + 4][ar] = pa1.x;
        As[0][aq * 4 + 5][ar] = pa1.y;
        As[0][aq * 4 + 6][ar] = pa1.z;
        As[0][aq * 4 + 7][ar] = pa1.w;
#pragma unroll
        for (int u = 0; u < 4; u++) {
            Bs[0][u * 4 + 0][br] = pb[u].x;
            Bs[0][u * 4 + 1][br] = pb[u].y;
            Bs[0][u * 4 + 2][br] = pb[u].z;
            Bs[0][u * 4 + 3][br] = pb[u].w;
        }
    }
    __syncthreads();

    const int NSTAGE = K_DIM / BK;   // 32
    for (int s = 0; s < NSTAGE; s++) {
        const int buf = s & 1;

        float4 pa0, pa1, pb[4];
        if (s < NSTAGE - 1) {
            const float* ap = Aptr + (s + 1) * BK;
            const float* bp = Bptr + (s + 1) * BK;
            pa0 = *reinterpret_cast<const float4*>(ap);
            pa1 = *reinterpret_cast<const float4*>(ap + 4);
#pragma unroll
            for (int u = 0; u < 4; u++)
                pb[u] = *reinterpret_cast<const float4*>(bp + u * 4);
        }

        // compute on buf
#pragma unroll
        for (int kk = 0; kk < BK; kk++) {
            float4 a0 = *reinterpret_cast<const float4*>(&As[buf][kk][ty * 8]);
            float4 a1 = *reinterpret_cast<const float4*>(&As[buf][kk][ty * 8 + 4]);
            float4 b0 = *reinterpret_cast<const float4*>(&Bs[buf][kk][tx * 8]);
            float4 b1 = *reinterpret_cast<const float4*>(&Bs[buf][kk][tx * 8 + 4]);
            float a[8] = {a0.x, a0.y, a0.z, a0.w, a1.x, a1.y, a1.z, a1.w};
            float b[8] = {b0.x, b0.y, b0.z, b0.w, b1.x, b1.y, b1.z, b1.w};
#pragma unroll
            for (int i = 0; i < 8; i++)
#pragma unroll
                for (int j = 0; j < 8; j++)
                    acc[i][j] = fmaf(a[i], b[j], acc[i][j]);
        }

        if (s < NSTAGE - 1) {
            const int nb = buf ^ 1;
            As[nb][aq * 4 + 0][ar] = pa0.x;
            As[nb][aq * 4 + 1][ar] = pa0.y;
            As[nb][aq * 4 + 2][ar] = pa0.z;
            As[nb][aq * 4 + 3][ar] = pa0.w;
            As[nb][aq * 4 + 4][ar] = pa1.x;
            As[nb][aq * 4 + 5][ar] = pa1.y;
            As[nb][aq * 4 + 6][ar] = pa1.z;
            As[nb][aq * 4 + 7][ar] = pa1.w;
#pragma unroll
            for (int u = 0; u < 4; u++) {
                Bs[nb][u * 4 + 0][br] = pb[u].x;
                Bs[nb][u * 4 + 1][br] = pb[u].y;
                Bs[nb][u * 4 + 2][br] = pb[u].z;
                Bs[nb][u * 4 + 3][br] = pb[u].w;
            }
            __syncthreads();
        }
    }

    // ---- epilogue: dist + argmin, reduce across tx, atomic merge ----
    float tsq[8];
#pragma unroll
    for (int j = 0; j < 8; j++) tsq[j] = g_tsq[col0 + tx * 8 + j];

#pragma unroll
    for (int i = 0; i < 8; i++) {
        const int row = row0 + ty * 8 + i;
        const float esq = g_esq[row];
        float best = 3.4e38f;
        int   bidx = 0x7FFFFFFF;
#pragma unroll
        for (int j = 0; j < 8; j++) {
            const int m = col0 + tx * 8 + j;
            float d = (esq - 2.0f * acc[i][j]) + tsq[j];
            if (d < best) { best = d; bidx = m; }   // m ascending -> first wins
        }
        // reduce across the 16 tx lanes (xor masks stay within same-ty half)
#pragma unroll
        for (int o = 1; o < 16; o <<= 1) {
            float ob = __shfl_xor_sync(0xffffffffu, best, o);
            int   oi = __shfl_xor_sync(0xffffffffu, bidx, o);
            if (ob < best || (ob == best && oi < bidx)) { best = ob; bidx = oi; }
        }
        if (tx == 0) {
            unsigned long long p =
                ((unsigned long long)__float_as_uint(best) << 32) |
                (unsigned int)bidx;
            atomicMin(&g_best[row], p);
        }
    }
}

// ---------------------------------------------------------------------------
// Gather: quant[n] = templat[idx]; optional float index tail.
// ---------------------------------------------------------------------------
__global__ void gather_kernel(const float* __restrict__ T,
                              float* __restrict__ outq,
                              float* __restrict__ outi,
                              int write_idx)
{
    int n = blockIdx.x;
    int zi = (int)(g_best[n] & 0xFFFFFFFFull);
    const float4* src = reinterpret_cast<const float4*>(T + (size_t)zi * K_DIM);
    float4* dst = reinterpret_cast<float4*>(outq + (size_t)n * K_DIM);
    dst[threadIdx.x] = src[threadIdx.x];
    if (write_idx && threadIdx.x == 0) outi[n] = (float)zi;
}

// ---------------------------------------------------------------------------
extern "C" void kernel_launch(void* const* d_in, const int* in_sizes, int n_in,
                              void* d_out, int out_size)
{
    const float* E = (const float*)d_in[0];  // (16384, 512)
    const float* T = (const float*)d_in[1];  // (2048, 512)
    float* out = (float*)d_out;

    init_best_kernel<<<N_TOK / 256, 256>>>();
    sqnorm_kernel<<<N_TOK / 8, 256>>>(E, N_TOK, 0);
    sqnorm_kernel<<<M_CODES / 8, 256>>>(T, M_CODES, 1);

    dim3 grid(N_TOK / BM, M_CODES / BN);
    argmin_gemm_kernel<<<grid, 128>>>(E, T);

    int write_idx = (out_size >= N_TOK * K_DIM + N_TOK) ? 1 : 0;
    float* outi = out + (size_t)N_TOK * K_DIM;
    gather_kernel<<<N_TOK, 128>>>(T, out, outi, write_idx);
}

// round 3
// speedup vs baseline: 1.7475x; 1.1110x over previous
#include <cuda_runtime.h>
#include <cuda_bf16.h>

#define K_DIM   512
#define N_TOK   16384
#define M_CODES 2048

__device__ float g_esq[N_TOK];
__device__ float g_tsq[M_CODES];
__device__ unsigned long long g_best[N_TOK];

// ---------------------------------------------------------------------------
__global__ void init_best_kernel() {
    int i = blockIdx.x * blockDim.x + threadIdx.x;
    if (i < N_TOK) g_best[i] = 0xFFFFFFFFFFFFFFFFull;
}

// ---------------------------------------------------------------------------
__global__ void sqnorm_kernel(const float* __restrict__ x, int rows, int which) {
    int warp = (blockIdx.x * blockDim.x + threadIdx.x) >> 5;
    int lane = threadIdx.x & 31;
    if (warp >= rows) return;
    const float* p = x + (size_t)warp * K_DIM;
    float s = 0.f;
#pragma unroll
    for (int i = 0; i < K_DIM / 32; i++) {
        float v = p[lane + i * 32];
        s = fmaf(v, v, s);
    }
#pragma unroll
    for (int o = 16; o > 0; o >>= 1) s += __shfl_xor_sync(0xffffffffu, s, o);
    if (lane == 0) {
        if (which == 0) g_esq[warp] = s;
        else            g_tsq[warp] = s;
    }
}

// ---------------------------------------------------------------------------
// Fused SGEMM + argmin. BM=64 x BN=128, BK=16 double-buffered, 128 threads,
// 8x8 micro-tile. Bank-conflict-free smem layout:
//  - B fragments: thread tx owns cols {tx*4..tx*4+3} and {64+tx*4..64+tx*4+3}
//    -> quarter-warp LDS.128 reads contiguous 128B.
//  - A store: ar=tid&63 (32 consecutive rows per warp) -> conflict-free STS.
// ---------------------------------------------------------------------------
#define BM 64
#define BN 128
#define BK 16
#define AST (BM + 4)   // 68
#define BST (BN + 4)   // 132

__global__ __launch_bounds__(128, 3) void argmin_gemm_kernel(
    const float* __restrict__ E, const float* __restrict__ T)
{
    __shared__ __align__(16) float As[2][BK][AST];
    __shared__ __align__(16) float Bs[2][BK][BST];

    const int tid = threadIdx.x;
    const int tx  = tid & 15;    // column group
    const int ty  = tid >> 4;    // row group (8 rows each)
    const int row0 = blockIdx.x * BM;
    const int col0 = blockIdx.y * BN;

    // A tile loads: 64 rows x 16 k; ar = tid & 63 (rows), aq selects k-half.
    const int ar = tid & 63;
    const int aq = (tid >> 6) * 2;        // float4 base index: 0 or 2
    // B tile loads: 128 rows x 16 k; 1 thread per row.
    const int br = tid;

    const float* Aptr = E + (size_t)(row0 + ar) * K_DIM + aq * 4;
    const float* Bptr = T + (size_t)(col0 + br) * K_DIM;

    float acc[8][8];
#pragma unroll
    for (int i = 0; i < 8; i++)
#pragma unroll
        for (int j = 0; j < 8; j++) acc[i][j] = 0.f;

    // ---- prologue: stage 0 -> buffer 0 ----
    {
        float4 pa0 = *reinterpret_cast<const float4*>(Aptr);
        float4 pa1 = *reinterpret_cast<const float4*>(Aptr + 4);
        float4 pb[4];
#pragma unroll
        for (int u = 0; u < 4; u++)
            pb[u] = *reinterpret_cast<const float4*>(Bptr + u * 4);

        As[0][aq * 4 + 0][ar] = pa0.x;
        As[0][aq * 4 + 1][ar] = pa0.y;
        As[0][aq * 4 + 2][ar] = pa0.z;
        As[0][aq * 4 + 3][ar] = pa0.w;
        As[0][aq * 4 + 4][ar] = pa1.x;
        As[0][aq * 4 + 5][ar] = pa1.y;
        As[0][aq * 4 + 6][ar] = pa1.z;
        As[0][aq * 4 + 7][ar] = pa1.w;
#pragma unroll
        for (int u = 0; u < 4; u++) {
            Bs[0][u * 4 + 0][br] = pb[u].x;
            Bs[0][u * 4 + 1][br] = pb[u].y;
            Bs[0][u * 4 + 2][br] = pb[u].z;
            Bs[0][u * 4 + 3][br] = pb[u].w;
        }
    }
    __syncthreads();

    const int NSTAGE = K_DIM / BK;   // 32
    for (int s = 0; s < NSTAGE; s++) {
        const int buf = s & 1;

        float4 pa0, pa1, pb[4];
        if (s < NSTAGE - 1) {
            const float* ap = Aptr + (s + 1) * BK;
            const float* bp = Bptr + (s + 1) * BK;
            pa0 = *reinterpret_cast<const float4*>(ap);
            pa1 = *reinterpret_cast<const float4*>(ap + 4);
#pragma unroll
            for (int u = 0; u < 4; u++)
                pb[u] = *reinterpret_cast<const float4*>(bp + u * 4);
        }

#pragma unroll
        for (int kk = 0; kk < BK; kk++) {
            float4 a0 = *reinterpret_cast<const float4*>(&As[buf][kk][ty * 8]);
            float4 a1 = *reinterpret_cast<const float4*>(&As[buf][kk][ty * 8 + 4]);
            // conflict-free: contiguous 128B per quarter-warp
            float4 b0 = *reinterpret_cast<const float4*>(&Bs[buf][kk][tx * 4]);
            float4 b1 = *reinterpret_cast<const float4*>(&Bs[buf][kk][64 + tx * 4]);
            float a[8] = {a0.x, a0.y, a0.z, a0.w, a1.x, a1.y, a1.z, a1.w};
            float b[8] = {b0.x, b0.y, b0.z, b0.w, b1.x, b1.y, b1.z, b1.w};
#pragma unroll
            for (int i = 0; i < 8; i++)
#pragma unroll
                for (int j = 0; j < 8; j++)
                    acc[i][j] = fmaf(a[i], b[j], acc[i][j]);
        }

        if (s < NSTAGE - 1) {
            const int nb = buf ^ 1;
            As[nb][aq * 4 + 0][ar] = pa0.x;
            As[nb][aq * 4 + 1][ar] = pa0.y;
            As[nb][aq * 4 + 2][ar] = pa0.z;
            As[nb][aq * 4 + 3][ar] = pa0.w;
            As[nb][aq * 4 + 4][ar] = pa1.x;
            As[nb][aq * 4 + 5][ar] = pa1.y;
            As[nb][aq * 4 + 6][ar] = pa1.z;
            As[nb][aq * 4 + 7][ar] = pa1.w;
#pragma unroll
            for (int u = 0; u < 4; u++) {
                Bs[nb][u * 4 + 0][br] = pb[u].x;
                Bs[nb][u * 4 + 1][br] = pb[u].y;
                Bs[nb][u * 4 + 2][br] = pb[u].z;
                Bs[nb][u * 4 + 3][br] = pb[u].w;
            }
            __syncthreads();
        }
    }

    // ---- epilogue ----
    // thread tx owns columns: j<4 -> tx*4+j ; j>=4 -> 64+tx*4+(j-4)
    float tsq[8];
#pragma unroll
    for (int j = 0; j < 8; j++) {
        int m = (j < 4) ? (tx * 4 + j) : (64 + tx * 4 + (j - 4));
        tsq[j] = g_tsq[col0 + m];
    }

#pragma unroll
    for (int i = 0; i < 8; i++) {
        const int row = row0 + ty * 8 + i;
        const float esq = g_esq[row];
        float best = 3.4e38f;
        int   bidx = 0x7FFFFFFF;
#pragma unroll
        for (int j = 0; j < 8; j++) {
            int m = col0 + ((j < 4) ? (tx * 4 + j) : (64 + tx * 4 + (j - 4)));
            float d = (esq - 2.0f * acc[i][j]) + tsq[j];
            if (d < best) { best = d; bidx = m; }   // per-thread m ascending
        }
#pragma unroll
        for (int o = 1; o < 16; o <<= 1) {
            float ob = __shfl_xor_sync(0xffffffffu, best, o);
            int   oi = __shfl_xor_sync(0xffffffffu, bidx, o);
            if (ob < best || (ob == best && oi < bidx)) { best = ob; bidx = oi; }
        }
        if (tx == 0) {
            unsigned long long p =
                ((unsigned long long)__float_as_uint(best) << 32) |
                (unsigned int)bidx;
            atomicMin(&g_best[row], p);
        }
    }
}

// ---------------------------------------------------------------------------
__global__ void gather_kernel(const float* __restrict__ T,
                              float* __restrict__ outq,
                              float* __restrict__ outi,
                              int write_idx)
{
    int n = blockIdx.x;
    int zi = (int)(g_best[n] & 0xFFFFFFFFull);
    const float4* src = reinterpret_cast<const float4*>(T + (size_t)zi * K_DIM);
    float4* dst = reinterpret_cast<float4*>(outq + (size_t)n * K_DIM);
    dst[threadIdx.x] = src[threadIdx.x];
    if (write_idx && threadIdx.x == 0) outi[n] = (float)zi;
}

// ---------------------------------------------------------------------------
extern "C" void kernel_launch(void* const* d_in, const int* in_sizes, int n_in,
                              void* d_out, int out_size)
{
    const float* E = (const float*)d_in[0];  // (16384, 512)
    const float* T = (const float*)d_in[1];  // (2048, 512)
    float* out = (float*)d_out;

    init_best_kernel<<<N_TOK / 256, 256>>>();
    sqnorm_kernel<<<N_TOK / 8, 256>>>(E, N_TOK, 0);
    sqnorm_kernel<<<M_CODES / 8, 256>>>(T, M_CODES, 1);

    dim3 grid(N_TOK / BM, M_CODES / BN);
    argmin_gemm_kernel<<<grid, 128>>>(E, T);

    int write_idx = (out_size >= N_TOK * K_DIM + N_TOK) ? 1 : 0;
    float* outi = out + (size_t)N_TOK * K_DIM;
    gather_kernel<<<N_TOK, 128>>>(T, out, outi, write_idx);
}